// round 9
// baseline (speedup 1.0000x reference)
#include <cuda_runtime.h>
#include <cuda_fp16.h>
#include <cstdint>
#include <cstddef>

#define BJ      8192
#define MDIM    4096
#define KDIM    4096
#define NADPT   4
#define DR      16
#define INV64   (1.0f / 64.0f)

// scratch: fp32 partial T (4 m-quarters, 8 MB) + pre-split packed A (1 MB)
__device__ float    g_Tp[4][NADPT * BJ * DR];
// A pre-split (x64 scaled): [row 64][chunk64 64][32 hi-pair words | 32 lo-pair words]
__device__ uint32_t g_Apk[64 * 64 * 64];

// ---------------------------------------------------------------------------
__device__ __forceinline__ float trunc10(float a) {   // keep 10 mantissa bits (exact fp16)
    return __uint_as_float(__float_as_uint(a) & 0xFFFFE000u);
}

// split f32 pair -> (hi half2, lo half2); hi = truncation (exact), lo = residual
__device__ __forceinline__ void split_pair(float v0, float v1, uint32_t& hi, uint32_t& lo) {
    float h0 = trunc10(v0), h1 = trunc10(v1);
    __half2 hh = __floats2half2_rn(h0, h1);            // exact
    __half2 ll = __floats2half2_rn(v0 - h0, v1 - h1);
    hi = *reinterpret_cast<uint32_t*>(&hh);
    lo = *reinterpret_cast<uint32_t*>(&ll);
}

__device__ __forceinline__ void mma16(float c[4], uint32_t a0, uint32_t a1, uint32_t a2,
                                      uint32_t a3, uint32_t b0, uint32_t b1) {
    asm volatile(
        "mma.sync.aligned.m16n8k16.row.col.f32.f16.f16.f32 "
        "{%0,%1,%2,%3}, {%4,%5,%6,%7}, {%8,%9}, {%0,%1,%2,%3};\n"
        : "+f"(c[0]), "+f"(c[1]), "+f"(c[2]), "+f"(c[3])
        : "r"(a0), "r"(a1), "r"(a2), "r"(a3), "r"(b0), "r"(b1));
}

__device__ __forceinline__ void cp16(uint32_t saddr, const void* g) {
    asm volatile("cp.async.cg.shared.global [%0], [%1], 16;\n" :: "r"(saddr), "l"(g));
}

__device__ __forceinline__ void stcs4(float* p, float4 v) {
    asm volatile("st.global.cs.v4.f32 [%0], {%1,%2,%3,%4};\n"
                 :: "l"(p), "f"(v.x), "f"(v.y), "f"(v.z), "f"(v.w));
}

// ---------------------------------------------------------------------------
// diagnostic alignment kernel (shifts ncu's sampled launch onto stage2)
__global__ void nop_kernel() {}

// ---------------------------------------------------------------------------
// prep: A[64][4096] * 64 -> truncation split, packed half2, chunk-64 layout
// ---------------------------------------------------------------------------
__global__ void split_A_kernel(const float* __restrict__ Aall) {
    int i = blockIdx.x * 256 + threadIdx.x;  // pair index, 131072 total
    int row = i >> 11, kp = i & 2047;        // kp = pair within row
    int chunk = kp >> 5, wi = kp & 31;       // 32 pairs per 64-float chunk
    float2 v = *(const float2*)&Aall[(size_t)row * MDIM + 2 * kp];
    uint32_t hi, lo;
    split_pair(v.x * 64.0f, v.y * 64.0f, hi, lo);
    uint32_t* dst = &g_Apk[((size_t)row * 64 + chunk) * 64];
    dst[wi]      = hi;
    dst[32 + wi] = lo;
}

// ---------------------------------------------------------------------------
// Stage 1: partial T over an M-quarter (1024). grid (128 bj, 4 m) x 256 thr.
// 8 warps = 2(wm) x 4(wn = adapter). Double-buffered smem, cp.async A,
// register-staged X with EAGER truncation split (split right after LDG so the
// FSUB/CVT overlap the mma loop). One __syncthreads per chunk.
// ---------------------------------------------------------------------------
__global__ __launch_bounds__(256)
void lora_stage1(const float* __restrict__ x) {
    extern __shared__ uint32_t smem[];
    uint32_t* Xs[2] = { smem,             smem + 64 * 68 };
    uint32_t* As[2] = { smem + 2*64*68,   smem + 3*64*68 };

    const int tid  = threadIdx.x;
    const int lane = tid & 31;
    const int warp = tid >> 5;
    const int gid  = lane >> 2;
    const int tig  = lane & 3;
    const int wm   = warp & 1;
    const int wn   = warp >> 1;
    const int bj0  = blockIdx.x * 64;
    const int my   = blockIdx.y;

    const int rx = tid >> 2;          // 0..63 (row)
    const int q  = tid & 3;           // quarter

    const float* xp = x + (size_t)(bj0 + rx) * MDIM + my * 1024 + q * 16;
    const int gc0 = my * 16;          // first global chunk

    float acc[2][2][4];
#pragma unroll
    for (int i = 0; i < 2; ++i)
#pragma unroll
        for (int j = 0; j < 2; ++j)
#pragma unroll
            for (int k = 0; k < 4; ++k) acc[i][j][k] = 0.f;

    uint32_t hx[8], lx[8];            // split X staged in registers
    auto ldg_split_x = [&](int c) {
        float4 xv[4];
#pragma unroll
        for (int j = 0; j < 4; ++j) xv[j] = *(const float4*)(xp + c * 64 + j * 4);
#pragma unroll
        for (int j = 0; j < 4; ++j) {
            split_pair(xv[j].x, xv[j].y, hx[2 * j],     lx[2 * j]);
            split_pair(xv[j].z, xv[j].w, hx[2 * j + 1], lx[2 * j + 1]);
        }
    };
    auto sts_x = [&](int buf) {
        const int qp = q * 8;   // pair base
        uint32_t* b = Xs[buf] + rx * 68 + qp;
        *(uint4*)(b)          = make_uint4(hx[0], hx[1], hx[2], hx[3]);
        *(uint4*)(b + 4)      = make_uint4(hx[4], hx[5], hx[6], hx[7]);
        *(uint4*)(b + 32)     = make_uint4(lx[0], lx[1], lx[2], lx[3]);
        *(uint4*)(b + 32 + 4) = make_uint4(lx[4], lx[5], lx[6], lx[7]);
    };
    auto cp_a = [&](int buf, int c) {
        const uint32_t* gsrc = g_Apk + ((size_t)rx * 64 + gc0 + c) * 64;
        uint32_t sbase = (uint32_t)__cvta_generic_to_shared(As[buf] + rx * 68);
#pragma unroll
        for (int i = 0; i < 4; ++i) {
            const int s = q + 4 * i;        // 16B segment 0..15
            cp16(sbase + s * 16, gsrc + s * 4);
        }
    };

    // prologue: chunk 0
    cp_a(0, 0);
    asm volatile("cp.async.commit_group;\n");
    ldg_split_x(0);
    sts_x(0);
    asm volatile("cp.async.wait_group 0;\n");
    __syncthreads();

    for (int c = 0; c < 16; ++c) {
        const int cur = c & 1;
        const bool more = (c + 1) < 16;
        if (more) {
            cp_a(cur ^ 1, c + 1);
            asm volatile("cp.async.commit_group;\n");
            ldg_split_x(c + 1);       // eager: split overlaps the mma loop below
        }

        const uint32_t* Xb = Xs[cur];
        const uint32_t* Ab = As[cur];
#pragma unroll
        for (int kki = 0; kki < 4; ++kki) {
            const int kb = kki * 8;
            uint32_t ah[2][4], al[2][4], bh[2][2], bl[2][2];
#pragma unroll
            for (int mi = 0; mi < 2; ++mi) {
                const uint32_t* p = Xb + (wm * 32 + mi * 16 + gid) * 68 + kb + tig;
                ah[mi][0] = p[0];  ah[mi][1] = p[8 * 68];
                ah[mi][2] = p[4];  ah[mi][3] = p[8 * 68 + 4];
                al[mi][0] = p[32]; al[mi][1] = p[8 * 68 + 32];
                al[mi][2] = p[36]; al[mi][3] = p[8 * 68 + 36];
            }
#pragma unroll
            for (int ni = 0; ni < 2; ++ni) {
                const uint32_t* p = Ab + (wn * 16 + ni * 8 + gid) * 68 + kb + tig;
                bh[ni][0] = p[0];  bh[ni][1] = p[4];
                bl[ni][0] = p[32]; bl[ni][1] = p[36];
            }
#pragma unroll
            for (int mi = 0; mi < 2; ++mi)
#pragma unroll
                for (int ni = 0; ni < 2; ++ni) {
                    mma16(acc[mi][ni], ah[mi][0], ah[mi][1], ah[mi][2], ah[mi][3], bh[ni][0], bh[ni][1]);
                    mma16(acc[mi][ni], al[mi][0], al[mi][1], al[mi][2], al[mi][3], bh[ni][0], bh[ni][1]);
                    mma16(acc[mi][ni], ah[mi][0], ah[mi][1], ah[mi][2], ah[mi][3], bl[ni][0], bl[ni][1]);
                }
        }

        if (more) {
            sts_x(cur ^ 1);
            asm volatile("cp.async.wait_group 0;\n");
        }
        __syncthreads();
    }

    // epilogue: unscale (A was x64) and write fp32 partials
    float* tp = g_Tp[my];
#pragma unroll
    for (int mi = 0; mi < 2; ++mi)
#pragma unroll
        for (int ni = 0; ni < 2; ++ni) {
            const int row = bj0 + wm * 32 + mi * 16 + gid;
            const int d   = ni * 8 + 2 * tig;
            float* dst = tp + ((size_t)(wn * BJ) + row) * DR + d;
            *(float2*)dst            = make_float2(acc[mi][ni][0] * INV64, acc[mi][ni][1] * INV64);
            *(float2*)(dst + 8 * DR) = make_float2(acc[mi][ni][2] * INV64, acc[mi][ni][3] * INV64);
        }
}

// ---------------------------------------------------------------------------
// Stage 2: Out_n = T_n @ B_n^T (d=16 = one mma-K). Block 128 bj x 128 k.
// 8 warps = 4(wm) x 2(wn); warp 32 x 64. fp16 packed, A-frags cached once,
// permuted B rows -> STG.128 (streaming .cs), sequential pi groups.
// ---------------------------------------------------------------------------
__global__ __launch_bounds__(256)
void lora_stage2(const float* __restrict__ Bm, float* __restrict__ out) {
    __shared__ uint32_t Ts[128 * 20];  // [8 hi pairs | 8 lo | pad 4]
    __shared__ uint32_t Bs[128 * 20];

    const int tid  = threadIdx.x;
    const int lane = tid & 31;
    const int warp = tid >> 5;
    const int gid  = lane >> 2;
    const int tig  = lane & 3;
    const int wn   = warp & 1;      // 2 warps over 128 k
    const int wm   = warp >> 1;     // 4 warps over 128 bj

    const int n   = blockIdx.z;
    const int bj0 = blockIdx.y * 128;
    const int k0  = blockIdx.x * 128;

    {   // T loader: sum 4 partials, truncation split
        const int r  = tid >> 1;
        const int cf = (tid & 1) * 8;
        const size_t base = ((size_t)(n * BJ) + bj0 + r) * DR + cf;
        float4 s0 = *(const float4*)&g_Tp[0][base];
        float4 s1 = *(const float4*)&g_Tp[0][base + 4];
#pragma unroll
        for (int p = 1; p < 4; ++p) {
            float4 a0 = *(const float4*)&g_Tp[p][base];
            float4 a1 = *(const float4*)&g_Tp[p][base + 4];
            s0.x += a0.x; s0.y += a0.y; s0.z += a0.z; s0.w += a0.w;
            s1.x += a1.x; s1.y += a1.y; s1.z += a1.z; s1.w += a1.w;
        }
        uint32_t h0, l0, h1, l1, h2, l2, h3, l3;
        split_pair(s0.x, s0.y, h0, l0);
        split_pair(s0.z, s0.w, h1, l1);
        split_pair(s1.x, s1.y, h2, l2);
        split_pair(s1.z, s1.w, h3, l3);
        const int pc = cf >> 1;
        *(uint4*)&Ts[r * 20 + pc]     = make_uint4(h0, h1, h2, h3);
        *(uint4*)&Ts[r * 20 + 8 + pc] = make_uint4(l0, l1, l2, l3);

        // B loader: x64 scale, split, permuted row so tig owns 4 consecutive cols
        const int rb = tid >> 1;
        const int bf = (tid & 1) * 8;
        const int gg = rb & 15, pgrp = rb >> 4;
        const int prow = pgrp * 16 + ((gg >> 1) & 1) * 8 + ((gg & 1) | ((gg >> 2) << 1));
        const float* bp = &Bm[((size_t)(n * KDIM) + k0 + rb) * DR + bf];
        float4 v0 = *(const float4*)bp;
        float4 v1 = *(const float4*)(bp + 4);
        uint32_t bh0, bl0, bh1, bl1, bh2, bl2, bh3, bl3;
        split_pair(v0.x * 64.f, v0.y * 64.f, bh0, bl0);
        split_pair(v0.z * 64.f, v0.w * 64.f, bh1, bl1);
        split_pair(v1.x * 64.f, v1.y * 64.f, bh2, bl2);
        split_pair(v1.z * 64.f, v1.w * 64.f, bh3, bl3);
        *(uint4*)&Bs[prow * 20 + pc]     = make_uint4(bh0, bh1, bh2, bh3);
        *(uint4*)&Bs[prow * 20 + 8 + pc] = make_uint4(bl0, bl1, bl2, bl3);
    }
    __syncthreads();

    // cache A-frags (whole d=16 = one mma-K) for all pi groups
    uint32_t ah[2][4], al[2][4];
#pragma unroll
    for (int mi = 0; mi < 2; ++mi) {
        const uint32_t* p = &Ts[(wm * 32 + mi * 16 + gid) * 20 + tig];
        ah[mi][0] = p[0];  ah[mi][1] = p[8 * 20];
        ah[mi][2] = p[4];  ah[mi][3] = p[8 * 20 + 4];
        al[mi][0] = p[8];  al[mi][1] = p[8 * 20 + 8];
        al[mi][2] = p[12]; al[mi][3] = p[8 * 20 + 12];
    }

#pragma unroll
    for (int pi = 0; pi < 4; ++pi) {
        float acc[2][2][4];
#pragma unroll
        for (int i = 0; i < 2; ++i)
#pragma unroll
            for (int t = 0; t < 2; ++t)
#pragma unroll
                for (int k = 0; k < 4; ++k) acc[i][t][k] = 0.f;

#pragma unroll
        for (int t = 0; t < 2; ++t) {
            const int brow = wn * 64 + pi * 16 + t * 8 + gid;
            const uint32_t* p = &Bs[brow * 20 + tig];
            const uint32_t bh0 = p[0], bh1 = p[4], bl0 = p[8], bl1 = p[12];
#pragma unroll
            for (int mi = 0; mi < 2; ++mi) {
                mma16(acc[mi][t], ah[mi][0], ah[mi][1], ah[mi][2], ah[mi][3], bh0, bh1);
                mma16(acc[mi][t], al[mi][0], al[mi][1], al[mi][2], al[mi][3], bh0, bh1);
                mma16(acc[mi][t], ah[mi][0], ah[mi][1], ah[mi][2], ah[mi][3], bl0, bl1);
            }
        }

#pragma unroll
        for (int mi = 0; mi < 2; ++mi) {
            const int row = bj0 + wm * 32 + mi * 16 + gid;
            const int col = k0 + wn * 64 + pi * 16 + 4 * tig;
            const size_t base = ((size_t)n * BJ + row) * (size_t)KDIM + col;
            float4 f0 = make_float4(acc[mi][0][0] * INV64, acc[mi][0][1] * INV64,
                                    acc[mi][1][0] * INV64, acc[mi][1][1] * INV64);
            float4 f1 = make_float4(acc[mi][0][2] * INV64, acc[mi][0][3] * INV64,
                                    acc[mi][1][2] * INV64, acc[mi][1][3] * INV64);
            stcs4(&out[base], f0);
            stcs4(&out[base + 8 * KDIM], f1);
        }
    }
}

// ---------------------------------------------------------------------------
extern "C" void kernel_launch(void* const* d_in, const int* in_sizes, int n_in,
                              void* d_out, int out_size) {
    const float* x    = (const float*)d_in[0];   // [8192, 4096]
    const float* Aall = (const float*)d_in[1];   // [64, 4096]
    const float* Bm   = (const float*)d_in[2];   // [4*4096, 16]
    float* out = (float*)d_out;                  // [4, 8192, 4096]

    const int s1_smem = 4 * 64 * 68 * 4;         // 69632 B
    cudaFuncSetAttribute(lora_stage1, cudaFuncAttributeMaxDynamicSharedMemorySize, s1_smem);

    nop_kernel<<<1, 1>>>();                      // slot alignment for ncu sampling
    split_A_kernel<<<512, 256>>>(Aall);
    lora_stage1<<<dim3(128, 4), 256, s1_smem>>>(x);
    lora_stage2<<<dim3(KDIM / 128, BJ / 128, NADPT), 256>>>(Bm, out);
}

// round 10
// speedup vs baseline: 1.0818x; 1.0818x over previous
#include <cuda_runtime.h>
#include <cuda_fp16.h>
#include <cstdint>
#include <cstddef>

#define BJ      8192
#define MDIM    4096
#define KDIM    4096
#define NADPT   4
#define DR      16
#define INV64   (1.0f / 64.0f)

// scratch: fp32 partial T (2 m-halves, 4 MB) + pre-split packed A (1 MB)
__device__ float    g_Tp[2][NADPT * BJ * DR];
// A pre-split (x64 scaled): [row 64][chunk64 64][32 hi-pair words | 32 lo-pair words]
__device__ uint32_t g_Apk[64 * 64 * 64];

// ---------------------------------------------------------------------------
__device__ __forceinline__ float trunc10(float a) {   // keep 10 mantissa bits (exact fp16)
    return __uint_as_float(__float_as_uint(a) & 0xFFFFE000u);
}

// split f32 pair -> (hi half2, lo half2); hi = truncation (exact), lo = residual
__device__ __forceinline__ void split_pair(float v0, float v1, uint32_t& hi, uint32_t& lo) {
    float h0 = trunc10(v0), h1 = trunc10(v1);
    __half2 hh = __floats2half2_rn(h0, h1);            // exact
    __half2 ll = __floats2half2_rn(v0 - h0, v1 - h1);
    hi = *reinterpret_cast<uint32_t*>(&hh);
    lo = *reinterpret_cast<uint32_t*>(&ll);
}

__device__ __forceinline__ void mma16(float c[4], uint32_t a0, uint32_t a1, uint32_t a2,
                                      uint32_t a3, uint32_t b0, uint32_t b1) {
    asm volatile(
        "mma.sync.aligned.m16n8k16.row.col.f32.f16.f16.f32 "
        "{%0,%1,%2,%3}, {%4,%5,%6,%7}, {%8,%9}, {%0,%1,%2,%3};\n"
        : "+f"(c[0]), "+f"(c[1]), "+f"(c[2]), "+f"(c[3])
        : "r"(a0), "r"(a1), "r"(a2), "r"(a3), "r"(b0), "r"(b1));
}

__device__ __forceinline__ void ldsm4(uint32_t& r0, uint32_t& r1, uint32_t& r2, uint32_t& r3,
                                      uint32_t saddr) {
    asm volatile("ldmatrix.sync.aligned.m8n8.x4.shared.b16 {%0,%1,%2,%3}, [%4];\n"
                 : "=r"(r0), "=r"(r1), "=r"(r2), "=r"(r3) : "r"(saddr));
}

__device__ __forceinline__ void cp16(uint32_t saddr, const void* g) {
    asm volatile("cp.async.cg.shared.global [%0], [%1], 16;\n" :: "r"(saddr), "l"(g));
}

__device__ __forceinline__ void stcs4(float* p, float4 v) {
    asm volatile("st.global.cs.v4.f32 [%0], {%1,%2,%3,%4};\n"
                 :: "l"(p), "f"(v.x), "f"(v.y), "f"(v.z), "f"(v.w));
}

// ---------------------------------------------------------------------------
__global__ void nop_kernel() {}

// ---------------------------------------------------------------------------
// prep: A[64][4096] * 64 -> truncation split, packed half2, chunk-64 layout
// ---------------------------------------------------------------------------
__global__ void split_A_kernel(const float* __restrict__ Aall) {
    int i = blockIdx.x * 256 + threadIdx.x;  // pair index, 131072 total
    int row = i >> 11, kp = i & 2047;        // kp = pair within row
    int chunk = kp >> 5, wi = kp & 31;       // 32 pairs per 64-float chunk
    float2 v = *(const float2*)&Aall[(size_t)row * MDIM + 2 * kp];
    uint32_t hi, lo;
    split_pair(v.x * 64.0f, v.y * 64.0f, hi, lo);
    uint32_t* dst = &g_Apk[((size_t)row * 64 + chunk) * 64];
    dst[wi]      = hi;
    dst[32 + wi] = lo;
}

// ---------------------------------------------------------------------------
// Stage 1: partial T over an M-half (2048). grid (128 bj, 2 m) x 256 thr.
// 8 warps = 2(wm) x 4(wn = adapter). Double-buffered smem, cp.async A,
// eager register-staged X split, ldmatrix fragment loads (6 LDSM.x4/kki).
// ---------------------------------------------------------------------------
__global__ __launch_bounds__(256)
void lora_stage1(const float* __restrict__ x) {
    extern __shared__ uint32_t smem[];

    const int tid  = threadIdx.x;
    const int lane = tid & 31;
    const int warp = tid >> 5;
    const int gid  = lane >> 2;
    const int tig  = lane & 3;
    const int wm   = warp & 1;
    const int wn   = warp >> 1;
    const int bj0  = blockIdx.x * 64;
    const int my   = blockIdx.y;

    const int mM = lane >> 3;         // ldmatrix matrix id (0..3)
    const int mr = lane & 7;          // ldmatrix row-in-matrix

    const int rx = tid >> 2;          // 0..63 (loader row)
    const int q  = tid & 3;           // loader quarter

    const float* xp = x + (size_t)(bj0 + rx) * MDIM + my * 2048 + q * 16;
    const int gc0 = my * 32;

    // ldmatrix per-lane base addresses (byte smem addresses)
    const uint32_t sb = (uint32_t)__cvta_generic_to_shared(smem);
    uint32_t xaddr[2][2], aaddr[2];
#pragma unroll
    for (int b = 0; b < 2; ++b) {
#pragma unroll
        for (int mi = 0; mi < 2; ++mi) {
            const int rowX = wm * 32 + mi * 16 + (mM & 1) * 8 + mr;
            xaddr[b][mi] = sb + (b * 64 * 68 + rowX * 68 + (mM >> 1) * 4) * 4;
        }
        const int rowA = wn * 16 + (mM >> 1) * 8 + mr;
        aaddr[b] = sb + ((2 + b) * 64 * 68 + rowA * 68 + (mM & 1) * 4) * 4;
    }
    uint32_t* Xs[2] = { smem,             smem + 64 * 68 };
    uint32_t* As[2] = { smem + 2*64*68,   smem + 3*64*68 };

    float acc[2][2][4];
#pragma unroll
    for (int i = 0; i < 2; ++i)
#pragma unroll
        for (int j = 0; j < 2; ++j)
#pragma unroll
            for (int k = 0; k < 4; ++k) acc[i][j][k] = 0.f;

    uint32_t hx[8], lx[8];
    auto ldg_split_x = [&](int c) {
        float4 xv[4];
#pragma unroll
        for (int j = 0; j < 4; ++j) xv[j] = *(const float4*)(xp + c * 64 + j * 4);
#pragma unroll
        for (int j = 0; j < 4; ++j) {
            split_pair(xv[j].x, xv[j].y, hx[2 * j],     lx[2 * j]);
            split_pair(xv[j].z, xv[j].w, hx[2 * j + 1], lx[2 * j + 1]);
        }
    };
    auto sts_x = [&](int buf) {
        const int qp = q * 8;
        uint32_t* b = Xs[buf] + rx * 68 + qp;
        *(uint4*)(b)          = make_uint4(hx[0], hx[1], hx[2], hx[3]);
        *(uint4*)(b + 4)      = make_uint4(hx[4], hx[5], hx[6], hx[7]);
        *(uint4*)(b + 32)     = make_uint4(lx[0], lx[1], lx[2], lx[3]);
        *(uint4*)(b + 32 + 4) = make_uint4(lx[4], lx[5], lx[6], lx[7]);
    };
    auto cp_a = [&](int buf, int c) {
        const uint32_t* gsrc = g_Apk + ((size_t)rx * 64 + gc0 + c) * 64;
        uint32_t sbase = (uint32_t)__cvta_generic_to_shared(As[buf] + rx * 68);
#pragma unroll
        for (int i = 0; i < 4; ++i) {
            const int s = q + 4 * i;
            cp16(sbase + s * 16, gsrc + s * 4);
        }
    };

    cp_a(0, 0);
    asm volatile("cp.async.commit_group;\n");
    ldg_split_x(0);
    sts_x(0);
    asm volatile("cp.async.wait_group 0;\n");
    __syncthreads();

    for (int c = 0; c < 32; ++c) {
        const int cur = c & 1;
        const bool more = (c + 1) < 32;
        if (more) {
            cp_a(cur ^ 1, c + 1);
            asm volatile("cp.async.commit_group;\n");
            ldg_split_x(c + 1);       // eager: overlaps the mma loop
        }

#pragma unroll
        for (int kki = 0; kki < 4; ++kki) {
            const uint32_t ko = kki * 32;   // byte offset: 8 words per kki
            uint32_t ah[2][4], al[2][4], bh[4], bl[4];
#pragma unroll
            for (int mi = 0; mi < 2; ++mi) {
                ldsm4(ah[mi][0], ah[mi][1], ah[mi][2], ah[mi][3], xaddr[cur][mi] + ko);
                ldsm4(al[mi][0], al[mi][1], al[mi][2], al[mi][3], xaddr[cur][mi] + ko + 128);
            }
            ldsm4(bh[0], bh[1], bh[2], bh[3], aaddr[cur] + ko);
            ldsm4(bl[0], bl[1], bl[2], bl[3], aaddr[cur] + ko + 128);
#pragma unroll
            for (int mi = 0; mi < 2; ++mi)
#pragma unroll
                for (int ni = 0; ni < 2; ++ni) {
                    mma16(acc[mi][ni], ah[mi][0], ah[mi][1], ah[mi][2], ah[mi][3], bh[2 * ni], bh[2 * ni + 1]);
                    mma16(acc[mi][ni], al[mi][0], al[mi][1], al[mi][2], al[mi][3], bh[2 * ni], bh[2 * ni + 1]);
                    mma16(acc[mi][ni], ah[mi][0], ah[mi][1], ah[mi][2], ah[mi][3], bl[2 * ni], bl[2 * ni + 1]);
                }
        }

        if (more) {
            sts_x(cur ^ 1);
            asm volatile("cp.async.wait_group 0;\n");
        }
        __syncthreads();
    }

    float* tp = g_Tp[my];
#pragma unroll
    for (int mi = 0; mi < 2; ++mi)
#pragma unroll
        for (int ni = 0; ni < 2; ++ni) {
            const int row = bj0 + wm * 32 + mi * 16 + gid;
            const int d   = ni * 8 + 2 * tig;
            float* dst = tp + ((size_t)(wn * BJ) + row) * DR + d;
            *(float2*)dst            = make_float2(acc[mi][ni][0] * INV64, acc[mi][ni][1] * INV64);
            *(float2*)(dst + 8 * DR) = make_float2(acc[mi][ni][2] * INV64, acc[mi][ni][3] * INV64);
        }
}

// ---------------------------------------------------------------------------
// Stage 2: Out_n = T_n @ B_n^T (d=16 = one mma-K). Block 128 bj x 128 k.
// 8 warps = 4(wm) x 2(wn); warp 32 x 64. ldmatrix fragment loads,
// permuted B rows -> STG.128 (.cs), sequential pi groups.
// ---------------------------------------------------------------------------
__global__ __launch_bounds__(256)
void lora_stage2(const float* __restrict__ Bm, float* __restrict__ out) {
    __shared__ uint32_t Ts[128 * 20];  // [8 hi pairs | 8 lo | pad 4]
    __shared__ uint32_t Bs[128 * 20];

    const int tid  = threadIdx.x;
    const int lane = tid & 31;
    const int warp = tid >> 5;
    const int gid  = lane >> 2;
    const int tig  = lane & 3;
    const int wn   = warp & 1;
    const int wm   = warp >> 1;
    const int mM = lane >> 3;
    const int mr = lane & 7;

    const int n   = blockIdx.z;
    const int bj0 = blockIdx.y * 128;
    const int k0  = blockIdx.x * 128;

    {   // T loader: sum 2 partials, truncation split
        const int r  = tid >> 1;
        const int cf = (tid & 1) * 8;
        const size_t base = ((size_t)(n * BJ) + bj0 + r) * DR + cf;
        float4 a0 = *(const float4*)&g_Tp[0][base];
        float4 a1 = *(const float4*)&g_Tp[0][base + 4];
        float4 b0 = *(const float4*)&g_Tp[1][base];
        float4 b1 = *(const float4*)&g_Tp[1][base + 4];
        float s0 = a0.x + b0.x, s1 = a0.y + b0.y, s2 = a0.z + b0.z, s3 = a0.w + b0.w;
        float s4 = a1.x + b1.x, s5 = a1.y + b1.y, s6 = a1.z + b1.z, s7 = a1.w + b1.w;
        uint32_t h0, l0, h1, l1, h2, l2, h3, l3;
        split_pair(s0, s1, h0, l0);
        split_pair(s2, s3, h1, l1);
        split_pair(s4, s5, h2, l2);
        split_pair(s6, s7, h3, l3);
        const int pc = cf >> 1;
        *(uint4*)&Ts[r * 20 + pc]     = make_uint4(h0, h1, h2, h3);
        *(uint4*)&Ts[r * 20 + 8 + pc] = make_uint4(l0, l1, l2, l3);

        // B loader: x64 scale, split, permuted row so tig owns 4 consecutive cols
        const int rb = tid >> 1;
        const int bf = (tid & 1) * 8;
        const int gg = rb & 15, pgrp = rb >> 4;
        const int prow = pgrp * 16 + ((gg >> 1) & 1) * 8 + ((gg & 1) | ((gg >> 2) << 1));
        const float* bp = &Bm[((size_t)(n * KDIM) + k0 + rb) * DR + bf];
        float4 v0 = *(const float4*)bp;
        float4 v1 = *(const float4*)(bp + 4);
        uint32_t bh0, bl0, bh1, bl1, bh2, bl2, bh3, bl3;
        split_pair(v0.x * 64.f, v0.y * 64.f, bh0, bl0);
        split_pair(v0.z * 64.f, v0.w * 64.f, bh1, bl1);
        split_pair(v1.x * 64.f, v1.y * 64.f, bh2, bl2);
        split_pair(v1.z * 64.f, v1.w * 64.f, bh3, bl3);
        *(uint4*)&Bs[prow * 20 + pc]     = make_uint4(bh0, bh1, bh2, bh3);
        *(uint4*)&Bs[prow * 20 + 8 + pc] = make_uint4(bl0, bl1, bl2, bl3);
    }
    __syncthreads();

    // A-frags via ldmatrix (once)
    uint32_t ah[2][4], al[2][4];
    {
        const uint32_t tb = (uint32_t)__cvta_generic_to_shared(Ts);
#pragma unroll
        for (int mi = 0; mi < 2; ++mi) {
            const int rowT = wm * 32 + mi * 16 + (mM & 1) * 8 + mr;
            const uint32_t ad = tb + (rowT * 20 + (mM >> 1) * 4) * 4;
            ldsm4(ah[mi][0], ah[mi][1], ah[mi][2], ah[mi][3], ad);
            ldsm4(al[mi][0], al[mi][1], al[mi][2], al[mi][3], ad + 32);
        }
    }
    const uint32_t bb = (uint32_t)__cvta_generic_to_shared(Bs)
                      + ((wn * 64 + (mM >> 1) * 8 + mr) * 20 + (mM & 1) * 4) * 4;

#pragma unroll
    for (int pi = 0; pi < 4; ++pi) {
        uint32_t bh[4], bl[4];
        ldsm4(bh[0], bh[1], bh[2], bh[3], bb + pi * 1280);
        ldsm4(bl[0], bl[1], bl[2], bl[3], bb + pi * 1280 + 32);

        float acc[2][2][4];
#pragma unroll
        for (int i = 0; i < 2; ++i)
#pragma unroll
            for (int t = 0; t < 2; ++t)
#pragma unroll
                for (int k = 0; k < 4; ++k) acc[i][t][k] = 0.f;

#pragma unroll
        for (int t = 0; t < 2; ++t)
#pragma unroll
            for (int mi = 0; mi < 2; ++mi) {
                mma16(acc[mi][t], ah[mi][0], ah[mi][1], ah[mi][2], ah[mi][3], bh[2 * t], bh[2 * t + 1]);
                mma16(acc[mi][t], al[mi][0], al[mi][1], al[mi][2], al[mi][3], bh[2 * t], bh[2 * t + 1]);
                mma16(acc[mi][t], ah[mi][0], ah[mi][1], ah[mi][2], ah[mi][3], bl[2 * t], bl[2 * t + 1]);
            }

#pragma unroll
        for (int mi = 0; mi < 2; ++mi) {
            const int row = bj0 + wm * 32 + mi * 16 + gid;
            const int col = k0 + wn * 64 + pi * 16 + 4 * tig;
            const size_t base = ((size_t)n * BJ + row) * (size_t)KDIM + col;
            float4 f0 = make_float4(acc[mi][0][0] * INV64, acc[mi][0][1] * INV64,
                                    acc[mi][1][0] * INV64, acc[mi][1][1] * INV64);
            float4 f1 = make_float4(acc[mi][0][2] * INV64, acc[mi][0][3] * INV64,
                                    acc[mi][1][2] * INV64, acc[mi][1][3] * INV64);
            stcs4(&out[base], f0);
            stcs4(&out[base + 8 * KDIM], f1);
        }
    }
}

// ---------------------------------------------------------------------------
extern "C" void kernel_launch(void* const* d_in, const int* in_sizes, int n_in,
                              void* d_out, int out_size) {
    const float* x    = (const float*)d_in[0];   // [8192, 4096]
    const float* Aall = (const float*)d_in[1];   // [64, 4096]
    const float* Bm   = (const float*)d_in[2];   // [4*4096, 16]
    float* out = (float*)d_out;                  // [4, 8192, 4096]

    const int s1_smem = 4 * 64 * 68 * 4;         // 69632 B
    cudaFuncSetAttribute(lora_stage1, cudaFuncAttributeMaxDynamicSharedMemorySize, s1_smem);

    nop_kernel<<<1, 1>>>();
    split_A_kernel<<<512, 256>>>(Aall);
    lora_stage1<<<dim3(128, 2), 256, s1_smem>>>(x);
    lora_stage2<<<dim3(KDIM / 128, BJ / 128, NADPT), 256>>>(Bm, out);
}